// round 2
// baseline (speedup 1.0000x reference)
#include <cuda_runtime.h>
#include <cuda_bf16.h>
#include <math_constants.h>

// Problem constants
#define BATCH 4
#define SEQ   2048
#define CH    256
#define HEADS 8
#define DH    32            // CH / HEADS
#define BH    (BATCH*HEADS) // 32
#define M_ROWS (BATCH*SEQ)  // 8192

// ---------------------------------------------------------------------------
// Scratch (no cudaMalloc allowed): Q/K/V in [BH, SEQ, DH], attn out in [B,N,C]
// ---------------------------------------------------------------------------
__device__ float g_q[BH * SEQ * DH];
__device__ float g_k[BH * SEQ * DH];
__device__ float g_v[BH * SEQ * DH];
__device__ float g_att[BATCH * SEQ * CH];

// ---------------------------------------------------------------------------
// Mask read helper: lengths are in [1,2048]. If the buffer is int64, the
// high word of value 0 (i.e. 32-bit word [1]) is 0; if int32, word [1] is a
// valid length >= 1. Branch on that, clamp for safety.
// ---------------------------------------------------------------------------
__device__ __forceinline__ int read_len(const void* kpm, int b)
{
    const int* p32 = (const int*)kpm;
    int len;
    if (p32[1] == 0) {                    // int64 layout
        len = (int)((const long long*)kpm)[b];
    } else {                              // int32 layout
        len = p32[b];
    }
    if (len < 1)   len = 1;
    if (len > SEQ) len = SEQ;
    return len;
}

// ---------------------------------------------------------------------------
// Kernel 1: QKV projection.  C[m,n] = sum_k X[m,k] * W[n,k]   (NT gemm)
//   X: [8192, 256]  W: [768, 256]
//   Scatter epilogue: n = s*256 + h*32 + d  ->  {g_q,g_k,g_v}[((b*8+h)*2048+nq)*32+d]
// 64x64 tile, BK=16, 256 threads, 4x4 per thread.
// ---------------------------------------------------------------------------
__global__ __launch_bounds__(256) void qkv_gemm_kernel(
    const float* __restrict__ X, const float* __restrict__ W)
{
    __shared__ float As[16][68];
    __shared__ float Bs[16][68];

    const int bm = blockIdx.x * 64;
    const int bn = blockIdx.y * 64;
    const int tid = threadIdx.x;

    const int la_r = tid >> 2;          // 0..63
    const int la_c = (tid & 3) * 4;     // 0,4,8,12

    const int tr = (tid >> 4) * 4;      // 0..60
    const int tc = (tid & 15) * 4;      // 0..60

    float acc[4][4];
#pragma unroll
    for (int i = 0; i < 4; i++)
#pragma unroll
        for (int j = 0; j < 4; j++) acc[i][j] = 0.f;

    for (int k0 = 0; k0 < 256; k0 += 16) {
        float4 av = *(const float4*)&X[(size_t)(bm + la_r) * 256 + k0 + la_c];
        float4 bv = *(const float4*)&W[(size_t)(bn + la_r) * 256 + k0 + la_c];
        __syncthreads();
        As[la_c + 0][la_r] = av.x; As[la_c + 1][la_r] = av.y;
        As[la_c + 2][la_r] = av.z; As[la_c + 3][la_r] = av.w;
        Bs[la_c + 0][la_r] = bv.x; Bs[la_c + 1][la_r] = bv.y;
        Bs[la_c + 2][la_r] = bv.z; Bs[la_c + 3][la_r] = bv.w;
        __syncthreads();
#pragma unroll
        for (int kk = 0; kk < 16; kk++) {
            float4 a = *(const float4*)&As[kk][tr];
            float4 b = *(const float4*)&Bs[kk][tc];
            float ar[4] = {a.x, a.y, a.z, a.w};
            float br[4] = {b.x, b.y, b.z, b.w};
#pragma unroll
            for (int i = 0; i < 4; i++)
#pragma unroll
                for (int j = 0; j < 4; j++) acc[i][j] += ar[i] * br[j];
        }
    }

    // scatter epilogue
#pragma unroll
    for (int i = 0; i < 4; i++) {
        const int m  = bm + tr + i;
        const int b  = m >> 11;          // /2048
        const int nq = m & 2047;
#pragma unroll
        for (int j = 0; j < 4; j++) {
            const int n = bn + tc + j;
            const int s = n >> 8;        // 0=q 1=k 2=v
            const int h = (n >> 5) & 7;
            const int d = n & 31;
            float* dst = (s == 0) ? g_q : ((s == 1) ? g_k : g_v);
            dst[(((size_t)(b * 8 + h)) * SEQ + nq) * DH + d] = acc[i][j];
        }
    }
}

// ---------------------------------------------------------------------------
// Kernel 2: flash attention with key-padding mask (early exit at len).
// 1 thread = 1 query row. 128 threads/block. K/V staged in smem 64-key tiles.
// Online softmax with lazy rescale (rescale o only when running max changes).
// ---------------------------------------------------------------------------
__global__ __launch_bounds__(128) void attn_kernel(const void* __restrict__ kpm)
{
    const int bh  = blockIdx.y;         // 0..31
    const int b   = bh >> 3;
    const int h   = bh & 7;
    const int row = blockIdx.x * 128 + threadIdx.x;   // 0..2047

    const int len = read_len(kpm, b);   // valid keys: 0..len-1  (clamped to [1,SEQ])
    const float scale = 0.17677669529663687f;  // 1/sqrt(32)

    // load q row into registers
    float q[DH];
    {
        const float* qp = g_q + ((size_t)bh * SEQ + row) * DH;
#pragma unroll
        for (int i = 0; i < 8; i++) {
            float4 t = *(const float4*)&qp[i * 4];
            q[i * 4 + 0] = t.x; q[i * 4 + 1] = t.y;
            q[i * 4 + 2] = t.z; q[i * 4 + 3] = t.w;
        }
    }

    float o[DH];
#pragma unroll
    for (int d = 0; d < DH; d++) o[d] = 0.f;
    float m = -CUDART_INF_F;
    float l = 0.f;

    __shared__ float ks[64][DH];
    __shared__ float vs[64][DH];

    const int ntiles = (len + 63) >> 6;
    for (int kt = 0; kt < ntiles; kt++) {
        __syncthreads();
        {
            const float4* kb = (const float4*)(g_k + ((size_t)bh * SEQ + kt * 64) * DH);
            const float4* vb = (const float4*)(g_v + ((size_t)bh * SEQ + kt * 64) * DH);
            float4* kd = (float4*)ks;
            float4* vd = (float4*)vs;
#pragma unroll
            for (int i = 0; i < 4; i++) {
                const int idx = threadIdx.x + i * 128;  // 0..511
                kd[idx] = kb[idx];
                vd[idx] = vb[idx];
            }
        }
        __syncthreads();

        const int jmax = min(64, len - kt * 64);
        for (int j = 0; j < jmax; j++) {
            const float* kj = ks[j];
            float s0 = 0.f, s1 = 0.f, s2 = 0.f, s3 = 0.f;
#pragma unroll
            for (int d = 0; d < DH; d += 4) {
                s0 += q[d + 0] * kj[d + 0];
                s1 += q[d + 1] * kj[d + 1];
                s2 += q[d + 2] * kj[d + 2];
                s3 += q[d + 3] * kj[d + 3];
            }
            float s = ((s0 + s1) + (s2 + s3)) * scale;

            if (s > m) {                     // rare after warmup
                float corr = __expf(m - s);  // exp(-inf)=0 on first hit
                l *= corr;
#pragma unroll
                for (int d = 0; d < DH; d++) o[d] *= corr;
                m = s;
            }
            float p = __expf(s - m);
            l += p;
            const float* vj = vs[j];
#pragma unroll
            for (int d = 0; d < DH; d++) o[d] += p * vj[d];
        }
    }

    const float inv = 1.f / l;
    float* op = g_att + ((size_t)(b * SEQ + row)) * CH + h * DH;
#pragma unroll
    for (int i = 0; i < 8; i++) {
        float4 t;
        t.x = o[i * 4 + 0] * inv; t.y = o[i * 4 + 1] * inv;
        t.z = o[i * 4 + 2] * inv; t.w = o[i * 4 + 3] * inv;
        *(float4*)&op[i * 4] = t;
    }
}

// ---------------------------------------------------------------------------
// Kernel 3: output projection + bias.  out[m,n] = sum_k att[m,k]*Wp[n,k] + bias[n]
//   att: [8192,256], Wp: [256,256]
// ---------------------------------------------------------------------------
__global__ __launch_bounds__(256) void proj_gemm_kernel(
    const float* __restrict__ Wp, const float* __restrict__ bias,
    float* __restrict__ out)
{
    __shared__ float As[16][68];
    __shared__ float Bs[16][68];

    const int bm = blockIdx.x * 64;
    const int bn = blockIdx.y * 64;
    const int tid = threadIdx.x;

    const int la_r = tid >> 2;
    const int la_c = (tid & 3) * 4;
    const int tr = (tid >> 4) * 4;
    const int tc = (tid & 15) * 4;

    float acc[4][4];
#pragma unroll
    for (int i = 0; i < 4; i++)
#pragma unroll
        for (int j = 0; j < 4; j++) acc[i][j] = 0.f;

    for (int k0 = 0; k0 < 256; k0 += 16) {
        float4 av = *(const float4*)&g_att[(size_t)(bm + la_r) * 256 + k0 + la_c];
        float4 bv = *(const float4*)&Wp[(size_t)(bn + la_r) * 256 + k0 + la_c];
        __syncthreads();
        As[la_c + 0][la_r] = av.x; As[la_c + 1][la_r] = av.y;
        As[la_c + 2][la_r] = av.z; As[la_c + 3][la_r] = av.w;
        Bs[la_c + 0][la_r] = bv.x; Bs[la_c + 1][la_r] = bv.y;
        Bs[la_c + 2][la_r] = bv.z; Bs[la_c + 3][la_r] = bv.w;
        __syncthreads();
#pragma unroll
        for (int kk = 0; kk < 16; kk++) {
            float4 a = *(const float4*)&As[kk][tr];
            float4 b = *(const float4*)&Bs[kk][tc];
            float ar[4] = {a.x, a.y, a.z, a.w};
            float br[4] = {b.x, b.y, b.z, b.w};
#pragma unroll
            for (int i = 0; i < 4; i++)
#pragma unroll
                for (int j = 0; j < 4; j++) acc[i][j] += ar[i] * br[j];
        }
    }

#pragma unroll
    for (int i = 0; i < 4; i++) {
        const int m = bm + tr + i;
#pragma unroll
        for (int j = 0; j < 4; j++) {
            const int n = bn + tc + j;
            out[(size_t)m * 256 + n] = acc[i][j] + bias[n];
        }
    }
}

// ---------------------------------------------------------------------------
// Launch: resolve inputs by element count (robust to ordering).
//   x: 4*2048*256 = 2097152, mask: 4, w_qkv: 768*256 = 196608,
//   w_proj: 256*256 = 65536, b_proj: 256
// ---------------------------------------------------------------------------
extern "C" void kernel_launch(void* const* d_in, const int* in_sizes, int n_in,
                              void* d_out, int out_size)
{
    (void)out_size;
    const float* x      = nullptr;
    const void*  kpm    = nullptr;
    const float* w_qkv  = nullptr;
    const float* w_proj = nullptr;
    const float* b_proj = nullptr;

    for (int i = 0; i < n_in; i++) {
        switch (in_sizes[i]) {
            case 2097152: x      = (const float*)d_in[i]; break;
            case 4:       kpm    = d_in[i];               break;
            case 196608:  w_qkv  = (const float*)d_in[i]; break;
            case 65536:   w_proj = (const float*)d_in[i]; break;
            case 256:     b_proj = (const float*)d_in[i]; break;
            default: break;
        }
    }
    float* out = (float*)d_out;   // [4,2048,256]

    {   // QKV projection: 8192 x 768
        dim3 grid(M_ROWS / 64, 768 / 64);
        qkv_gemm_kernel<<<grid, 256>>>(x, w_qkv);
    }
    {   // attention: 128 query rows per block, 32 (b,h) pairs
        dim3 grid(SEQ / 128, BH);
        attn_kernel<<<grid, 128>>>(kpm);
    }
    {   // output projection: 8192 x 256
        dim3 grid(M_ROWS / 64, 256 / 64);
        proj_gemm_kernel<<<grid, 256>>>(w_proj, b_proj, out);
    }
}

// round 4
// speedup vs baseline: 1.1297x; 1.1297x over previous
#include <cuda_runtime.h>
#include <cuda_bf16.h>
#include <math_constants.h>

#define BATCH 4
#define SEQ   2048
#define CH    256
#define HEADS 8
#define DH    32
#define BH    (BATCH*HEADS)
#define M_ROWS (BATCH*SEQ)

__device__ float g_q[BH * SEQ * DH];
__device__ float g_k[BH * SEQ * DH];
__device__ float g_v[BH * SEQ * DH];
__device__ float g_att[BATCH * SEQ * CH];

// Mask: lengths in [1,2048]; int64 vs int32 sniff (word[1]==0 => int64).
__device__ __forceinline__ int read_len(const void* kpm, int b)
{
    const int* p32 = (const int*)kpm;
    int len = (p32[1] == 0) ? (int)((const long long*)kpm)[b] : p32[b];
    if (len < 1)   len = 1;
    if (len > SEQ) len = SEQ;
    return len;
}

// ---------------------------------------------------------------------------
// Epilogue functors (no extended-lambda support in harness nvcc)
// ---------------------------------------------------------------------------
struct QkvEpilogue {
    __device__ __forceinline__ void operator()(
        int bm_, int bn_, const int* roff, const int* coff,
        float (&acc)[8][8]) const
    {
#pragma unroll
        for (int i = 0; i < 8; i++) {
            const int m  = bm_ + roff[i];
            const int b  = m >> 11;
            const int nq = m & 2047;
#pragma unroll
            for (int j = 0; j < 8; j++) {
                const int n = bn_ + coff[j];
                const int s = n >> 8;        // 0=q 1=k 2=v
                const int h = (n >> 5) & 7;
                const int d = n & 31;
                float* dst = (s == 0) ? g_q : ((s == 1) ? g_k : g_v);
                dst[(((size_t)(b * 8 + h)) * SEQ + nq) * DH + d] = acc[i][j];
            }
        }
    }
};

struct ProjEpilogue {
    float* out;
    const float* bias;
    __device__ __forceinline__ void operator()(
        int bm_, int bn_, const int* roff, const int* coff,
        float (&acc)[8][8]) const
    {
#pragma unroll
        for (int i = 0; i < 8; i++) {
            const int m = bm_ + roff[i];
#pragma unroll
            for (int j = 0; j < 8; j++) {
                const int n = bn_ + coff[j];
                out[(size_t)m * 256 + n] = acc[i][j] + bias[n];
            }
        }
    }
};

// ---------------------------------------------------------------------------
// 128x128x8 double-buffered NT GEMM body: C[m,n] = sum_k A[m,k]*B[n,k]
// 256 threads, 8x8 per thread in 4x(4x4) quadrants. One sync per k-step.
// ---------------------------------------------------------------------------
template <typename Epilogue>
__device__ __forceinline__ void gemm128x128(
    const float* __restrict__ A, const float* __restrict__ B,
    int bm, int bn, const Epilogue& epi)
{
    __shared__ __align__(16) float As[2][8][132];
    __shared__ __align__(16) float Bs[2][8][132];

    const int tid = threadIdx.x;
    const int lr = tid >> 1;          // 0..127
    const int lc = (tid & 1) * 4;     // 0 or 4
    const int tr0 = (tid >> 4) * 4;   // 0..60
    const int tc0 = (tid & 15) * 4;   // 0..60

    float acc[8][8];
#pragma unroll
    for (int i = 0; i < 8; i++)
#pragma unroll
        for (int j = 0; j < 8; j++) acc[i][j] = 0.f;

    // prologue: tile 0
    float4 av = *(const float4*)&A[(size_t)(bm + lr) * 256 + lc];
    float4 bv = *(const float4*)&B[(size_t)(bn + lr) * 256 + lc];
    As[0][lc + 0][lr] = av.x; As[0][lc + 1][lr] = av.y;
    As[0][lc + 2][lr] = av.z; As[0][lc + 3][lr] = av.w;
    Bs[0][lc + 0][lr] = bv.x; Bs[0][lc + 1][lr] = bv.y;
    Bs[0][lc + 2][lr] = bv.z; Bs[0][lc + 3][lr] = bv.w;
    __syncthreads();

    int buf = 0;
    for (int k0 = 0; k0 < 256; k0 += 8) {
        const int nxt = k0 + 8;
        float4 an, bn4;
        if (nxt < 256) {
            an  = *(const float4*)&A[(size_t)(bm + lr) * 256 + nxt + lc];
            bn4 = *(const float4*)&B[(size_t)(bn + lr) * 256 + nxt + lc];
        }
#pragma unroll
        for (int kk = 0; kk < 8; kk++) {
            float4 a0 = *(const float4*)&As[buf][kk][tr0];
            float4 a1 = *(const float4*)&As[buf][kk][tr0 + 64];
            float4 b0 = *(const float4*)&Bs[buf][kk][tc0];
            float4 b1 = *(const float4*)&Bs[buf][kk][tc0 + 64];
            float ar[8] = {a0.x, a0.y, a0.z, a0.w, a1.x, a1.y, a1.z, a1.w};
            float br[8] = {b0.x, b0.y, b0.z, b0.w, b1.x, b1.y, b1.z, b1.w};
#pragma unroll
            for (int i = 0; i < 8; i++)
#pragma unroll
                for (int j = 0; j < 8; j++) acc[i][j] += ar[i] * br[j];
        }
        if (nxt < 256) {
            const int nb = buf ^ 1;
            As[nb][lc + 0][lr] = an.x;  As[nb][lc + 1][lr] = an.y;
            As[nb][lc + 2][lr] = an.z;  As[nb][lc + 3][lr] = an.w;
            Bs[nb][lc + 0][lr] = bn4.x; Bs[nb][lc + 1][lr] = bn4.y;
            Bs[nb][lc + 2][lr] = bn4.z; Bs[nb][lc + 3][lr] = bn4.w;
            buf = nb;
            __syncthreads();
        }
    }

    // row/col offsets of the 8x8 quadrant layout
    int roff[8], coff[8];
#pragma unroll
    for (int i = 0; i < 4; i++) {
        roff[i] = tr0 + i;      roff[i + 4] = tr0 + 64 + i;
        coff[i] = tc0 + i;      coff[i + 4] = tc0 + 64 + i;
    }
    epi(bm, bn, roff, coff, acc);
}

// ---------------------------------------------------------------------------
// Kernel 1: QKV projection (scatter into g_q/g_k/g_v [BH,SEQ,DH])
// ---------------------------------------------------------------------------
__global__ __launch_bounds__(256) void qkv_gemm_kernel(
    const float* __restrict__ X, const float* __restrict__ W)
{
    const int bm = blockIdx.x * 128;
    const int bn = blockIdx.y * 128;
    QkvEpilogue epi;
    gemm128x128(X, W, bm, bn, epi);
}

// ---------------------------------------------------------------------------
// Kernel 3: output projection + bias
// ---------------------------------------------------------------------------
__global__ __launch_bounds__(256) void proj_gemm_kernel(
    const float* __restrict__ Wp, const float* __restrict__ bias,
    float* __restrict__ out)
{
    const int bm = blockIdx.x * 128;
    const int bn = blockIdx.y * 128;
    ProjEpilogue epi{out, bias};
    gemm128x128(g_att, Wp, bm, bn, epi);
}

// ---------------------------------------------------------------------------
// Kernel 2: flash attention, 1 thread = 1 query row, chunked branch-free
// softmax: 16 scores in regs -> max tree -> one uniform rescale -> exp+PV.
// ---------------------------------------------------------------------------
__global__ __launch_bounds__(128) void attn_kernel(const void* __restrict__ kpm)
{
    const int bh  = blockIdx.y;
    const int b   = bh >> 3;
    const int h   = bh & 7;
    const int row = blockIdx.x * 128 + threadIdx.x;

    const int len = read_len(kpm, b);
    const float scale = 0.17677669529663687f;   // 1/sqrt(32)

    float q[DH];
    {
        const float4* qp = (const float4*)(g_q + ((size_t)bh * SEQ + row) * DH);
#pragma unroll
        for (int i = 0; i < 8; i++) {
            float4 t = qp[i];
            q[i*4+0] = t.x; q[i*4+1] = t.y; q[i*4+2] = t.z; q[i*4+3] = t.w;
        }
    }

    float o[DH];
#pragma unroll
    for (int d = 0; d < DH; d++) o[d] = 0.f;
    float m = -CUDART_INF_F;
    float l = 0.f;

    __shared__ __align__(16) float ks[64][DH];
    __shared__ __align__(16) float vs[64][DH];

    const int ntiles = (len + 63) >> 6;
    for (int kt = 0; kt < ntiles; kt++) {
        __syncthreads();
        {
            const float4* kb = (const float4*)(g_k + ((size_t)bh * SEQ + kt * 64) * DH);
            const float4* vb = (const float4*)(g_v + ((size_t)bh * SEQ + kt * 64) * DH);
            float4* kd = (float4*)ks;
            float4* vd = (float4*)vs;
#pragma unroll
            for (int i = 0; i < 4; i++) {
                const int idx = threadIdx.x + i * 128;
                kd[idx] = kb[idx];
                vd[idx] = vb[idx];
            }
        }
        __syncthreads();

        const int jmax = min(64, len - kt * 64);
#pragma unroll 1
        for (int c = 0; c < 64; c += 16) {
            if (c >= jmax) break;
            float s[16];
#pragma unroll
            for (int jj = 0; jj < 16; jj++) {
                const float4* kj = (const float4*)ks[c + jj];
                float s0 = 0.f, s1 = 0.f, s2 = 0.f, s3 = 0.f;
#pragma unroll
                for (int i = 0; i < 8; i++) {
                    float4 kv = kj[i];
                    s0 += q[i*4+0] * kv.x;
                    s1 += q[i*4+1] * kv.y;
                    s2 += q[i*4+2] * kv.z;
                    s3 += q[i*4+3] * kv.w;
                }
                float sv = ((s0 + s1) + (s2 + s3)) * scale;
                s[jj] = (c + jj < jmax) ? sv : -CUDART_INF_F;
            }
            // branchless chunk max
            float cmax = s[0];
#pragma unroll
            for (int jj = 1; jj < 16; jj++) cmax = fmaxf(cmax, s[jj]);
            const float newm = fmaxf(m, cmax);
            const float corr = __expf(m - newm);   // exp(-inf)=0 on first chunk
            l *= corr;
#pragma unroll
            for (int d = 0; d < DH; d++) o[d] *= corr;
            m = newm;

#pragma unroll
            for (int jj = 0; jj < 16; jj++) {
                const float p = __expf(s[jj] - m);
                l += p;
                const float4* vj = (const float4*)vs[c + jj];
#pragma unroll
                for (int i = 0; i < 8; i++) {
                    float4 vv = vj[i];
                    o[i*4+0] += p * vv.x;
                    o[i*4+1] += p * vv.y;
                    o[i*4+2] += p * vv.z;
                    o[i*4+3] += p * vv.w;
                }
            }
        }
    }

    const float inv = 1.f / l;
    float4* op = (float4*)(g_att + ((size_t)(b * SEQ + row)) * CH + h * DH);
#pragma unroll
    for (int i = 0; i < 8; i++) {
        float4 t;
        t.x = o[i*4+0] * inv; t.y = o[i*4+1] * inv;
        t.z = o[i*4+2] * inv; t.w = o[i*4+3] * inv;
        op[i] = t;
    }
}

// ---------------------------------------------------------------------------
// Launch: resolve inputs by element count.
// ---------------------------------------------------------------------------
extern "C" void kernel_launch(void* const* d_in, const int* in_sizes, int n_in,
                              void* d_out, int out_size)
{
    (void)out_size;
    const float* x = nullptr; const void* kpm = nullptr;
    const float* w_qkv = nullptr; const float* w_proj = nullptr;
    const float* b_proj = nullptr;

    for (int i = 0; i < n_in; i++) {
        switch (in_sizes[i]) {
            case 2097152: x      = (const float*)d_in[i]; break;
            case 4:       kpm    = d_in[i];               break;
            case 196608:  w_qkv  = (const float*)d_in[i]; break;
            case 65536:   w_proj = (const float*)d_in[i]; break;
            case 256:     b_proj = (const float*)d_in[i]; break;
            default: break;
        }
    }
    float* out = (float*)d_out;

    {   // QKV: 8192 x 768
        dim3 grid(M_ROWS / 128, 768 / 128);
        qkv_gemm_kernel<<<grid, 256>>>(x, w_qkv);
    }
    {   // attention
        dim3 grid(SEQ / 128, BH);
        attn_kernel<<<grid, 128>>>(kpm);
    }
    {   // proj: 8192 x 256
        dim3 grid(M_ROWS / 128, 256 / 128);
        proj_gemm_kernel<<<grid, 256>>>(w_proj, b_proj, out);
    }
}